// round 5
// baseline (speedup 1.0000x reference)
#include <cuda_runtime.h>
#include <cstdint>

#define W129 129
#define NPIX (129*129)

// ---------------- scratch (device globals — no allocation allowed) ----------
__device__ float g_ups[2*2*128*NPIX];      // [b][frame][c][pix]
__device__ float g_wt_reduce[128*9*256];   // [ic][rs][oc]
__device__ float g_wt_conv2[512*9*256];    // [ic][rs][oc]
__device__ float g_concat[2*512*NPIX];     // [b][frame*256+oc][pix]
__device__ float g_y[2*256*NPIX];          // [b][oc][pix]
__device__ float g_ker[2*49*NPIX];         // [b][o][pix]

// ---------------- weight transpose: OIHW -> [IC][9][OC], OC=256 -------------
__global__ void transpose_w_kernel(const float* __restrict__ src,
                                   float* __restrict__ dst, int IC) {
    int idx = blockIdx.x * blockDim.x + threadIdx.x;
    int total = IC * 9 * 256;
    if (idx >= total) return;
    int oc = idx & 255;
    int rs = (idx >> 8) % 9;
    int ic = idx / (256 * 9);
    dst[idx] = src[(size_t)oc * IC * 9 + ic * 9 + rs];
}

// ---------------- bilinear upsample 33x33 -> 129x129 (half-pixel) -----------
__global__ void upsample_kernel(const float* __restrict__ cur,
                                const float* __restrict__ key,
                                float* __restrict__ out) {
    int idx = blockIdx.x * blockDim.x + threadIdx.x;
    const int total = 2 * 2 * 128 * NPIX;
    if (idx >= total) return;
    int x = idx % W129;
    int y = (idx / W129) % W129;
    int c = (idx / NPIX) % 128;
    int frame = (idx / (NPIX * 128)) & 1;
    int b = idx / (NPIX * 128 * 2);
    const float* src = (frame == 0 ? cur : key) + ((size_t)b * 128 + c) * 33 * 33;
    const float scale = 33.0f / 129.0f;
    float sy = fminf(fmaxf((y + 0.5f) * scale - 0.5f, 0.0f), 32.0f);
    float sx = fminf(fmaxf((x + 0.5f) * scale - 0.5f, 0.0f), 32.0f);
    int y0 = (int)sy, x0 = (int)sx;
    int y1 = min(y0 + 1, 32), x1 = min(x0 + 1, 32);
    float fy = sy - (float)y0, fx = sx - (float)x0;
    float v00 = src[y0 * 33 + x0], v01 = src[y0 * 33 + x1];
    float v10 = src[y1 * 33 + x0], v11 = src[y1 * 33 + x1];
    float v0 = v00 + (v01 - v00) * fx;
    float v1 = v10 + (v11 - v10) * fx;
    out[idx] = v0 + (v1 - v0) * fy;
}

// ---------------- 3x3 conv + bias + relu, implicit-GEMM tiling --------------
// block tile: 128 oc x (8 rows x 16 cols) pixels; thread micro-tile 8x8.
// in:  [nimg][IC][NPIX], wt: [IC][9][256], out: [nimg][256][NPIX]
template<int IC>
__launch_bounds__(256, 2)
__global__ void conv3x3_kernel(const float* __restrict__ in,
                               const float* __restrict__ wt,
                               const float* __restrict__ bias,
                               float* __restrict__ out) {
    __shared__ __align__(16) float s_in[8][10][18];
    __shared__ __align__(16) float s_w[8][9][128];

    const int tid = threadIdx.x;
    const int tx  = tid & 15;     // pixel column within tile
    const int ty  = tid >> 4;     // oc group (0..15)

    const int col0 = blockIdx.x * 16;
    const int row0 = blockIdx.y * 8;
    const int z    = blockIdx.z;
    const int ocbase = (z & 1) * 128;
    const int img    = z >> 1;

    const float* in_img  = in  + (size_t)img * IC  * NPIX;
    float*       out_img = out + (size_t)img * 256 * NPIX;

    float acc[8][8];
#pragma unroll
    for (int i = 0; i < 8; i++)
#pragma unroll
        for (int j = 0; j < 8; j++) acc[i][j] = 0.0f;

    for (int ic0 = 0; ic0 < IC; ic0 += 8) {
        __syncthreads();
        // input chunk: 8 ic x 10 rows x 18 cols
        for (int idx = tid; idx < 8 * 180; idx += 256) {
            int c  = idx % 18;
            int r  = (idx / 18) % 10;
            int ic = idx / 180;
            int gr = row0 - 1 + r;
            int gc = col0 - 1 + c;
            float v = 0.0f;
            if ((unsigned)gr < 129u && (unsigned)gc < 129u)
                v = in_img[(size_t)(ic0 + ic) * NPIX + gr * W129 + gc];
            s_in[ic][r][c] = v;
        }
        // weight chunk: 8 ic x 9 rs x 128 oc (as float4)
        float4* wdst = reinterpret_cast<float4*>(&s_w[0][0][0]);
        for (int idx = tid; idx < 8 * 9 * 32; idx += 256) {
            int q   = idx & 31;     // float4 within 128 oc
            int row = idx >> 5;     // ic*9 + rs
            wdst[idx] = reinterpret_cast<const float4*>(
                wt + ((size_t)ic0 * 9 + row) * 256 + ocbase)[q];
        }
        __syncthreads();

#pragma unroll 1
        for (int ic = 0; ic < 8; ic++) {
#pragma unroll
            for (int r = 0; r < 3; r++) {
#pragma unroll
                for (int s = 0; s < 3; s++) {
                    float a[8], bfr[8];
                    float4 a0 = *reinterpret_cast<const float4*>(&s_w[ic][r * 3 + s][ty * 8]);
                    float4 a1 = *reinterpret_cast<const float4*>(&s_w[ic][r * 3 + s][ty * 8 + 4]);
                    a[0] = a0.x; a[1] = a0.y; a[2] = a0.z; a[3] = a0.w;
                    a[4] = a1.x; a[5] = a1.y; a[6] = a1.z; a[7] = a1.w;
#pragma unroll
                    for (int i = 0; i < 8; i++) bfr[i] = s_in[ic][i + r][tx + s];
#pragma unroll
                    for (int j = 0; j < 8; j++)
#pragma unroll
                        for (int i = 0; i < 8; i++)
                            acc[i][j] += bfr[i] * a[j];
                }
            }
        }
    }

#pragma unroll
    for (int j = 0; j < 8; j++) {
        int oc = ocbase + ty * 8 + j;
        float bb = bias[oc];
#pragma unroll
        for (int i = 0; i < 8; i++) {
            int gr = row0 + i, gc = col0 + tx;
            if (gr < 129 && gc < 129) {
                float v = acc[i][j] + bb;
                out_img[(size_t)oc * NPIX + gr * W129 + gc] = fmaxf(v, 0.0f);
            }
        }
    }
}

// ---------------- 1x1 conv (256->49) + bias + relu + softmax ----------------
__launch_bounds__(256)
__global__ void conv1x1_softmax_kernel(const float* __restrict__ y,
                                       const float* __restrict__ w,   // [49][256]
                                       const float* __restrict__ bias,
                                       float* __restrict__ ker) {
    __shared__ float s_w[49 * 64];
    const int img = blockIdx.y;
    int p = blockIdx.x * 256 + threadIdx.x;
    const bool valid = p < NPIX;
    if (!valid) p = NPIX - 1;
    const float* y_img = y + (size_t)img * 256 * NPIX;

    float acc[49];
#pragma unroll
    for (int o = 0; o < 49; o++) acc[o] = 0.0f;

    for (int ic0 = 0; ic0 < 256; ic0 += 64) {
        __syncthreads();
        for (int idx = threadIdx.x; idx < 49 * 64; idx += 256) {
            int o = idx / 64, i = idx % 64;
            s_w[idx] = w[o * 256 + ic0 + i];
        }
        __syncthreads();
#pragma unroll 2
        for (int ic = 0; ic < 64; ic++) {
            float x = y_img[(size_t)(ic0 + ic) * NPIX + p];
#pragma unroll
            for (int o = 0; o < 49; o++) acc[o] += x * s_w[o * 64 + ic];
        }
    }

    float m = -1e30f;
#pragma unroll
    for (int o = 0; o < 49; o++) {
        acc[o] = fmaxf(acc[o] + bias[o], 0.0f);
        m = fmaxf(m, acc[o]);
    }
    float sum = 0.0f;
#pragma unroll
    for (int o = 0; o < 49; o++) {
        acc[o] = expf(acc[o] - m);
        sum += acc[o];
    }
    float inv = 1.0f / sum;
    if (valid) {
        float* k_img = ker + (size_t)img * 49 * NPIX;
#pragma unroll
        for (int o = 0; o < 49; o++)
            k_img[(size_t)o * NPIX + p] = acc[o] * inv;
    }
}

// ---------------- spatially-variant 7x7 conv --------------------------------
__launch_bounds__(256)
__global__ void svconv_kernel(const float* __restrict__ f,    // [2][256][NPIX]
                              const float* __restrict__ ker,  // [2][49][NPIX]
                              float* __restrict__ out) {      // [2][256][NPIX]
    __shared__ float s_f[8][22][22];
    const int tx = threadIdx.x & 15, ty = threadIdx.x >> 4;
    const int col0 = blockIdx.x * 16, row0 = blockIdx.y * 16;
    const int z = blockIdx.z;
    const int c_base = (z & 3) * 64;
    const int img = z >> 2;

    const int gy = row0 + ty, gx = col0 + tx;
    const bool valid = (gy < 129) && (gx < 129);
    const float* f_img = f   + (size_t)img * 256 * NPIX;
    const float* k_img = ker + (size_t)img * 49  * NPIX;
    float*       o_img = out + (size_t)img * 256 * NPIX;

    float kv[49];
    int pclamp = valid ? gy * W129 + gx : 0;
#pragma unroll
    for (int o = 0; o < 49; o++) kv[o] = k_img[(size_t)o * NPIX + pclamp];

    for (int cc = 0; cc < 64; cc += 8) {
        __syncthreads();
        for (int idx = threadIdx.x; idx < 8 * 22 * 22; idx += 256) {
            int cx = idx % 22;
            int cy = (idx / 22) % 22;
            int ch = idx / 484;
            int gr = row0 - 3 + cy, gc = col0 - 3 + cx;
            float v = 0.0f;
            if ((unsigned)gr < 129u && (unsigned)gc < 129u)
                v = f_img[(size_t)(c_base + cc + ch) * NPIX + gr * W129 + gc];
            s_f[ch][cy][cx] = v;
        }
        __syncthreads();
#pragma unroll 1
        for (int ch = 0; ch < 8; ch++) {
            float acc = 0.0f;
#pragma unroll
            for (int i = 0; i < 7; i++)
#pragma unroll
                for (int j = 0; j < 7; j++)
                    acc += kv[i * 7 + j] * s_f[ch][ty + i][tx + j];
            if (valid)
                o_img[(size_t)(c_base + cc + ch) * NPIX + gy * W129 + gx] = acc;
        }
    }
}

// ---------------- launch -----------------------------------------------------
extern "C" void kernel_launch(void* const* d_in, const int* in_sizes, int n_in,
                              void* d_out, int out_size) {
    const float* cur      = (const float*)d_in[0];
    const float* key      = (const float*)d_in[1];
    const float* high     = (const float*)d_in[2];
    const float* w_reduce = (const float*)d_in[3];
    const float* b_reduce = (const float*)d_in[4];
    const float* w_conv2  = (const float*)d_in[5];
    const float* b_conv2  = (const float*)d_in[6];
    const float* w_conv3  = (const float*)d_in[7];
    const float* b_conv3  = (const float*)d_in[8];
    float* out = (float*)d_out;

    float *ups, *wtr, *wt2, *ccat, *yb, *kb;
    cudaGetSymbolAddress((void**)&ups,  g_ups);
    cudaGetSymbolAddress((void**)&wtr,  g_wt_reduce);
    cudaGetSymbolAddress((void**)&wt2,  g_wt_conv2);
    cudaGetSymbolAddress((void**)&ccat, g_concat);
    cudaGetSymbolAddress((void**)&yb,   g_y);
    cudaGetSymbolAddress((void**)&kb,   g_ker);

    // 1. transpose weights to [IC][9][256]
    {
        int t1 = 128 * 9 * 256;
        transpose_w_kernel<<<(t1 + 255) / 256, 256>>>(w_reduce, wtr, 128);
        int t2 = 512 * 9 * 256;
        transpose_w_kernel<<<(t2 + 255) / 256, 256>>>(w_conv2, wt2, 512);
    }
    // 2. upsample both frames
    {
        int total = 2 * 2 * 128 * NPIX;
        upsample_kernel<<<(total + 255) / 256, 256>>>(cur, key, ups);
    }
    // 3. conv_reduce (4 images, 128->256) -> concat buffer
    {
        dim3 grid(9, 17, 8);   // 9 col tiles, 17 row tiles, 4 imgs * 2 oc blocks
        conv3x3_kernel<128><<<grid, 256>>>(ups, wtr, b_reduce, ccat);
    }
    // 4. conv2 (2 images, 512->256)
    {
        dim3 grid(9, 17, 4);
        conv3x3_kernel<512><<<grid, 256>>>(ccat, wt2, b_conv2, yb);
    }
    // 5. 1x1 conv + softmax -> kernels
    {
        dim3 grid((NPIX + 255) / 256, 2);
        conv1x1_softmax_kernel<<<grid, 256>>>(yb, w_conv3, b_conv3, kb);
    }
    // 6. spatially-variant 7x7 conv -> output
    {
        dim3 grid(9, 9, 8);    // 9x9 spatial tiles, 2 imgs * 4 channel groups
        svconv_kernel<<<grid, 256>>>(high, kb, out);
    }
}

// round 6
// speedup vs baseline: 1.5187x; 1.5187x over previous
#include <cuda_runtime.h>
#include <cstdint>

#define W129 129
#define NPIX (129*129)

// ---------------- scratch (device globals — no allocation allowed) ----------
__device__ float g_ups[2*2*128*NPIX];      // [b][frame][c][pix]
__device__ float g_wt_reduce[128*9*256];   // [ic][rs][oc]
__device__ float g_wt_conv2[512*9*256];    // [ic][rs][oc]
__device__ float g_concat[2*512*NPIX];     // [b][frame*256+oc][pix]
__device__ float g_y[2*256*NPIX];          // [b][oc][pix]
__device__ float g_ker[2*49*NPIX];         // [b][o][pix]

// ---------------- weight transpose: OIHW -> [IC][9][OC], OC=256 -------------
__global__ void transpose_w_kernel(const float* __restrict__ src,
                                   float* __restrict__ dst, int IC) {
    int idx = blockIdx.x * blockDim.x + threadIdx.x;
    int total = IC * 9 * 256;
    if (idx >= total) return;
    int oc = idx & 255;
    int rs = (idx >> 8) % 9;
    int ic = idx / (256 * 9);
    dst[idx] = src[(size_t)oc * IC * 9 + ic * 9 + rs];
}

// ---------------- bilinear upsample 33x33 -> 129x129 (half-pixel) -----------
__global__ void upsample_kernel(const float* __restrict__ cur,
                                const float* __restrict__ key,
                                float* __restrict__ out) {
    int idx = blockIdx.x * blockDim.x + threadIdx.x;
    const int total = 2 * 2 * 128 * NPIX;
    if (idx >= total) return;
    int x = idx % W129;
    int y = (idx / W129) % W129;
    int c = (idx / NPIX) % 128;
    int frame = (idx / (NPIX * 128)) & 1;
    int b = idx / (NPIX * 128 * 2);
    const float* src = (frame == 0 ? cur : key) + ((size_t)b * 128 + c) * 33 * 33;
    const float scale = 33.0f / 129.0f;
    float sy = fminf(fmaxf((y + 0.5f) * scale - 0.5f, 0.0f), 32.0f);
    float sx = fminf(fmaxf((x + 0.5f) * scale - 0.5f, 0.0f), 32.0f);
    int y0 = (int)sy, x0 = (int)sx;
    int y1 = min(y0 + 1, 32), x1 = min(x0 + 1, 32);
    float fy = sy - (float)y0, fx = sx - (float)x0;
    float v00 = src[y0 * 33 + x0], v01 = src[y0 * 33 + x1];
    float v10 = src[y1 * 33 + x0], v11 = src[y1 * 33 + x1];
    float v0 = v00 + (v01 - v00) * fx;
    float v1 = v10 + (v11 - v10) * fx;
    out[idx] = v0 + (v1 - v0) * fy;
}

// ---------------- 3x3 conv + bias + relu, implicit-GEMM tiling --------------
// block tile: 128 oc x (8 rows x 16 cols) pixels; thread micro-tile 8x8.
// in:  [nimg][IC][NPIX], wt: [IC][9][256], out: [nimg][256][NPIX]
template<int IC>
__launch_bounds__(256, 2)
__global__ void conv3x3_kernel(const float* __restrict__ in,
                               const float* __restrict__ wt,
                               const float* __restrict__ bias,
                               float* __restrict__ out) {
    __shared__ __align__(16) float s_in[8][10][18];
    __shared__ __align__(16) float s_w[8][9][128];

    const int tid = threadIdx.x;
    const int tx  = tid & 15;     // pixel column within tile
    const int ty  = tid >> 4;     // oc group (0..15)

    const int col0 = blockIdx.x * 16;
    const int row0 = blockIdx.y * 8;
    const int z    = blockIdx.z;
    const int ocbase = (z & 1) * 128;
    const int img    = z >> 1;

    const float* in_img  = in  + (size_t)img * IC  * NPIX;
    float*       out_img = out + (size_t)img * 256 * NPIX;

    float acc[8][8];
#pragma unroll
    for (int i = 0; i < 8; i++)
#pragma unroll
        for (int j = 0; j < 8; j++) acc[i][j] = 0.0f;

    for (int ic0 = 0; ic0 < IC; ic0 += 8) {
        __syncthreads();
        // input chunk: 8 ic x 10 rows x 18 cols
        for (int idx = tid; idx < 8 * 180; idx += 256) {
            int c  = idx % 18;
            int r  = (idx / 18) % 10;
            int ic = idx / 180;
            int gr = row0 - 1 + r;
            int gc = col0 - 1 + c;
            float v = 0.0f;
            if ((unsigned)gr < 129u && (unsigned)gc < 129u)
                v = in_img[(size_t)(ic0 + ic) * NPIX + gr * W129 + gc];
            s_in[ic][r][c] = v;
        }
        // weight chunk: 8 ic x 9 rs x 128 oc (as float4)
        float4* wdst = reinterpret_cast<float4*>(&s_w[0][0][0]);
        for (int idx = tid; idx < 8 * 9 * 32; idx += 256) {
            int q   = idx & 31;     // float4 within 128 oc
            int row = idx >> 5;     // ic*9 + rs
            wdst[idx] = reinterpret_cast<const float4*>(
                wt + ((size_t)ic0 * 9 + row) * 256 + ocbase)[q];
        }
        __syncthreads();

#pragma unroll 1
        for (int ic = 0; ic < 8; ic++) {
#pragma unroll
            for (int r = 0; r < 3; r++) {
#pragma unroll
                for (int s = 0; s < 3; s++) {
                    float a[8], bfr[8];
                    float4 a0 = *reinterpret_cast<const float4*>(&s_w[ic][r * 3 + s][ty * 8]);
                    float4 a1 = *reinterpret_cast<const float4*>(&s_w[ic][r * 3 + s][ty * 8 + 4]);
                    a[0] = a0.x; a[1] = a0.y; a[2] = a0.z; a[3] = a0.w;
                    a[4] = a1.x; a[5] = a1.y; a[6] = a1.z; a[7] = a1.w;
#pragma unroll
                    for (int i = 0; i < 8; i++) bfr[i] = s_in[ic][i + r][tx + s];
#pragma unroll
                    for (int j = 0; j < 8; j++)
#pragma unroll
                        for (int i = 0; i < 8; i++)
                            acc[i][j] += bfr[i] * a[j];
                }
            }
        }
    }

#pragma unroll
    for (int j = 0; j < 8; j++) {
        int oc = ocbase + ty * 8 + j;
        float bb = bias[oc];
#pragma unroll
        for (int i = 0; i < 8; i++) {
            int gr = row0 + i, gc = col0 + tx;
            if (gr < 129 && gc < 129) {
                float v = acc[i][j] + bb;
                out_img[(size_t)oc * NPIX + gr * W129 + gc] = fmaxf(v, 0.0f);
            }
        }
    }
}

// ---------------- 1x1 conv (256->49) + bias + relu + softmax ----------------
__launch_bounds__(256)
__global__ void conv1x1_softmax_kernel(const float* __restrict__ y,
                                       const float* __restrict__ w,   // [49][256]
                                       const float* __restrict__ bias,
                                       float* __restrict__ ker) {
    __shared__ float s_w[49 * 64];
    const int img = blockIdx.y;
    int p = blockIdx.x * 256 + threadIdx.x;
    const bool valid = p < NPIX;
    if (!valid) p = NPIX - 1;
    const float* y_img = y + (size_t)img * 256 * NPIX;

    float acc[49];
#pragma unroll
    for (int o = 0; o < 49; o++) acc[o] = 0.0f;

    for (int ic0 = 0; ic0 < 256; ic0 += 64) {
        __syncthreads();
        for (int idx = threadIdx.x; idx < 49 * 64; idx += 256) {
            int o = idx / 64, i = idx % 64;
            s_w[idx] = w[o * 256 + ic0 + i];
        }
        __syncthreads();
#pragma unroll 2
        for (int ic = 0; ic < 64; ic++) {
            float x = y_img[(size_t)(ic0 + ic) * NPIX + p];
#pragma unroll
            for (int o = 0; o < 49; o++) acc[o] += x * s_w[o * 64 + ic];
        }
    }

    float m = -1e30f;
#pragma unroll
    for (int o = 0; o < 49; o++) {
        acc[o] = fmaxf(acc[o] + bias[o], 0.0f);
        m = fmaxf(m, acc[o]);
    }
    float sum = 0.0f;
#pragma unroll
    for (int o = 0; o < 49; o++) {
        acc[o] = expf(acc[o] - m);
        sum += acc[o];
    }
    float inv = 1.0f / sum;
    if (valid) {
        float* k_img = ker + (size_t)img * 49 * NPIX;
#pragma unroll
        for (int o = 0; o < 49; o++)
            k_img[(size_t)o * NPIX + p] = acc[o] * inv;
    }
}

// ---------------- spatially-variant 7x7 conv --------------------------------
__launch_bounds__(256)
__global__ void svconv_kernel(const float* __restrict__ f,    // [2][256][NPIX]
                              const float* __restrict__ ker,  // [2][49][NPIX]
                              float* __restrict__ out) {      // [2][256][NPIX]
    __shared__ float s_f[8][22][22];
    const int tx = threadIdx.x & 15, ty = threadIdx.x >> 4;
    const int col0 = blockIdx.x * 16, row0 = blockIdx.y * 16;
    const int z = blockIdx.z;
    const int c_base = (z & 3) * 64;
    const int img = z >> 2;

    const int gy = row0 + ty, gx = col0 + tx;
    const bool valid = (gy < 129) && (gx < 129);
    const float* f_img = f   + (size_t)img * 256 * NPIX;
    const float* k_img = ker + (size_t)img * 49  * NPIX;
    float*       o_img = out + (size_t)img * 256 * NPIX;

    float kv[49];
    int pclamp = valid ? gy * W129 + gx : 0;
#pragma unroll
    for (int o = 0; o < 49; o++) kv[o] = k_img[(size_t)o * NPIX + pclamp];

    for (int cc = 0; cc < 64; cc += 8) {
        __syncthreads();
        for (int idx = threadIdx.x; idx < 8 * 22 * 22; idx += 256) {
            int cx = idx % 22;
            int cy = (idx / 22) % 22;
            int ch = idx / 484;
            int gr = row0 - 3 + cy, gc = col0 - 3 + cx;
            float v = 0.0f;
            if ((unsigned)gr < 129u && (unsigned)gc < 129u)
                v = f_img[(size_t)(c_base + cc + ch) * NPIX + gr * W129 + gc];
            s_f[ch][cy][cx] = v;
        }
        __syncthreads();
#pragma unroll 1
        for (int ch = 0; ch < 8; ch++) {
            float acc = 0.0f;
#pragma unroll
            for (int i = 0; i < 7; i++)
#pragma unroll
                for (int j = 0; j < 7; j++)
                    acc += kv[i * 7 + j] * s_f[ch][ty + i][tx + j];
            if (valid)
                o_img[(size_t)(c_base + cc + ch) * NPIX + gy * W129 + gx] = acc;
        }
    }
}

// ---------------- launch -----------------------------------------------------
extern "C" void kernel_launch(void* const* d_in, const int* in_sizes, int n_in,
                              void* d_out, int out_size) {
    const float* cur      = (const float*)d_in[0];
    const float* key      = (const float*)d_in[1];
    const float* high     = (const float*)d_in[2];
    const float* w_reduce = (const float*)d_in[3];
    const float* b_reduce = (const float*)d_in[4];
    const float* w_conv2  = (const float*)d_in[5];
    const float* b_conv2  = (const float*)d_in[6];
    const float* w_conv3  = (const float*)d_in[7];
    const float* b_conv3  = (const float*)d_in[8];
    float* out = (float*)d_out;

    float *ups, *wtr, *wt2, *ccat, *yb, *kb;
    cudaGetSymbolAddress((void**)&ups,  g_ups);
    cudaGetSymbolAddress((void**)&wtr,  g_wt_reduce);
    cudaGetSymbolAddress((void**)&wt2,  g_wt_conv2);
    cudaGetSymbolAddress((void**)&ccat, g_concat);
    cudaGetSymbolAddress((void**)&yb,   g_y);
    cudaGetSymbolAddress((void**)&kb,   g_ker);

    // 1. transpose weights to [IC][9][256]
    {
        int t1 = 128 * 9 * 256;
        transpose_w_kernel<<<(t1 + 255) / 256, 256>>>(w_reduce, wtr, 128);
        int t2 = 512 * 9 * 256;
        transpose_w_kernel<<<(t2 + 255) / 256, 256>>>(w_conv2, wt2, 512);
    }
    // 2. upsample both frames
    {
        int total = 2 * 2 * 128 * NPIX;
        upsample_kernel<<<(total + 255) / 256, 256>>>(cur, key, ups);
    }
    // 3. conv_reduce (4 images, 128->256) -> concat buffer
    {
        dim3 grid(9, 17, 8);   // 9 col tiles, 17 row tiles, 4 imgs * 2 oc blocks
        conv3x3_kernel<128><<<grid, 256>>>(ups, wtr, b_reduce, ccat);
    }
    // 4. conv2 (2 images, 512->256)
    {
        dim3 grid(9, 17, 4);
        conv3x3_kernel<512><<<grid, 256>>>(ccat, wt2, b_conv2, yb);
    }
    // 5. 1x1 conv + softmax -> kernels
    {
        dim3 grid((NPIX + 255) / 256, 2);
        conv1x1_softmax_kernel<<<grid, 256>>>(yb, w_conv3, b_conv3, kb);
    }
    // 6. spatially-variant 7x7 conv -> output
    {
        dim3 grid(9, 9, 8);    // 9x9 spatial tiles, 2 imgs * 4 channel groups
        svconv_kernel<<<grid, 256>>>(high, kb, out);
    }
}

// round 10
// speedup vs baseline: 5.4166x; 3.5667x over previous
#include <cuda_runtime.h>
#include <cstdint>

#define W129 129
#define NPIX (129*129)
#define PW   131
#define PADROWS 17792
#define MT128 133          // ceil(16899/128) M-tiles of 128

// ---------------- scratch (device globals) ----------------------------------
__device__ float g_ups[4u*PADROWS*128];     // [img][padpos][128] NHWC, tf32 vals
__device__ float g_ccat[2u*PADROWS*512];    // [b][padpos][512]   NHWC, tf32 vals
__device__ float g_wtr[9*256*128];          // [rs][oc][ic] tf32
__device__ float g_wt2[9*256*512];          // [rs][oc][ic] tf32
__device__ float g_y[2u*NPIX*256];          // [img][pix][256] fp32 NHWC
__device__ float g_ker[2*49*NPIX];          // [img][o][pix]

// ========================= helpers ==========================================
__device__ __forceinline__ float tf32r(float x) {
    asm("cvt.rna.tf32.f32 %0, %0;" : "+f"(x));
    return x;
}
__device__ __forceinline__ uint32_t smem_u32(const void* p) {
    uint32_t a;
    asm("{ .reg .u64 t; cvta.to.shared.u64 t, %1; cvt.u32.u64 %0, t; }" : "=r"(a) : "l"(p));
    return a;
}
__device__ __forceinline__ void cp_async16(uint32_t dst, const void* src) {
    asm volatile("cp.async.cg.shared.global [%0], [%1], 16;" :: "r"(dst), "l"(src) : "memory");
}
__device__ __forceinline__ void cp_commit() {
    asm volatile("cp.async.commit_group;" ::: "memory");
}
__device__ __forceinline__ void mma_tf32_16x8x8(float* c, const uint32_t* a, const uint32_t* b) {
    asm volatile(
        "mma.sync.aligned.m16n8k8.row.col.f32.tf32.tf32.f32 "
        "{%0,%1,%2,%3}, {%4,%5,%6,%7}, {%8,%9}, {%0,%1,%2,%3};"
        : "+f"(c[0]), "+f"(c[1]), "+f"(c[2]), "+f"(c[3])
        : "r"(a[0]), "r"(a[1]), "r"(a[2]), "r"(a[3]), "r"(b[0]), "r"(b[1]));
}

// ========================= aux kernels ======================================
__global__ void zero_kernel(float4* a, size_t na, float4* b, size_t nb) {
    size_t i = (size_t)blockIdx.x * blockDim.x + threadIdx.x;
    size_t stride = (size_t)gridDim.x * blockDim.x;
    float4 z = make_float4(0.f, 0.f, 0.f, 0.f);
    for (size_t k = i; k < na; k += stride) a[k] = z;
    for (size_t k = i; k < nb; k += stride) b[k] = z;
}

__global__ void transpose_w_tf32(const float* __restrict__ src,
                                 float* __restrict__ dst, int IC) {
    int idx = blockIdx.x * blockDim.x + threadIdx.x;
    int total = 9 * 256 * IC;
    if (idx >= total) return;
    int ic = idx % IC;
    int oc = (idx / IC) % 256;
    int rs = idx / (IC * 256);
    dst[idx] = tf32r(src[((size_t)oc * IC + ic) * 9 + rs]);
}

__global__ __launch_bounds__(256) void upsample_nhwc(const float* __restrict__ cur,
                                                     const float* __restrict__ key,
                                                     float* __restrict__ ups) {
    __shared__ float s[128][2][33];
    int y = blockIdx.x;          // 0..128
    int img = blockIdx.y;        // 0..3
    int b = img >> 1, frame = img & 1;
    const float* src = (frame ? key : cur) + (size_t)b * 128 * 1089;
    const float scale = 33.0f / 129.0f;
    float sy = fminf(fmaxf((y + 0.5f) * scale - 0.5f, 0.0f), 32.0f);
    int y0 = (int)sy, y1 = min(y0 + 1, 32);
    float fy = sy - (float)y0;
    for (int idx = threadIdx.x; idx < 128 * 66; idx += 256) {
        int c = idx / 66, rem = idx % 66;
        int yy = rem / 33, x = rem % 33;
        s[c][yy][x] = src[c * 1089 + (yy ? y1 : y0) * 33 + x];
    }
    __syncthreads();
    float* dst = ups + ((size_t)img * PADROWS + (size_t)(y + 1) * PW + 1) * 128;
    for (int e = threadIdx.x; e < 129 * 128; e += 256) {
        int x = e >> 7, c = e & 127;
        float sx = fminf(fmaxf((x + 0.5f) * scale - 0.5f, 0.0f), 32.0f);
        int x0 = (int)sx, x1 = min(x0 + 1, 32);
        float fx = sx - (float)x0;
        float v0 = s[c][0][x0] + (s[c][0][x1] - s[c][0][x0]) * fx;
        float v1 = s[c][1][x0] + (s[c][1][x1] - s[c][1][x0]) * fx;
        dst[(size_t)x * 128 + c] = tf32r(v0 + (v1 - v0) * fy);
    }
}

// ============== warp-MMA tf32 implicit-GEMM 3x3 conv ========================
// CTA: M=128 padded-grid positions x N=128 oc. 8 warps, each 64x32.
// K-chunks of 32 ic per tap; double-buffered cp.async.
// smem per buffer: A 128x36, B 128x36 floats (stride-36 pad -> conflict-free)
#define SK 36
#define BUFBYTES (2 * 128 * SK * 4)   // A+B one stage = 36864

template<int IC, bool TO_CCAT>
__global__ __launch_bounds__(256, 2)
void conv_mma_kernel(const float* __restrict__ in,
                     const float* __restrict__ wt,
                     const float* __restrict__ bias,
                     float* __restrict__ outbuf) {
    extern __shared__ float dsm[];

    const int tid = threadIdx.x;
    const int wid = tid >> 5;
    const int lane = tid & 31;
    const int r = lane >> 2;         // 0..7
    const int cth = lane & 3;        // 0..3

    const int q0 = blockIdx.x * 128;
    const int img = blockIdx.y;
    const int ocbase = blockIdx.z * 128;
    const int wm = wid & 1;          // m-half (64)
    const int wn = wid >> 1;         // n-quarter (32)

    const float* in_img = in + (size_t)img * PADROWS * IC;
    const uint32_t smem0 = smem_u32(dsm);

    const int KC = IC / 32;          // ic-chunks per tap
    const int NK = 9 * KC;

    float c[4][4][4];
#pragma unroll
    for (int mt = 0; mt < 4; mt++)
#pragma unroll
        for (int nt = 0; nt < 4; nt++)
#pragma unroll
            for (int v = 0; v < 4; v++) c[mt][nt][v] = 0.0f;

    const int l_row = tid >> 3;      // 0..31... per-iteration row offset base
    const int l_k4  = tid & 7;       // float4 index within 32 floats

    // ---- chunk loader ----
    auto issue_chunk = [&](int ch, int buf) {
        int rs = ch / KC, icc = ch % KC;
        int dq = (rs / 3) * PW + (rs % 3);
        int ic0 = icc * 32;
        uint32_t As = smem0 + buf * BUFBYTES;
        uint32_t Bs = As + 128 * SK * 4;
        const float* gA = in_img + (size_t)(q0 + dq) * IC + ic0;
        const float* gB = wt + ((size_t)rs * 256 + ocbase) * IC + ic0;
#pragma unroll
        for (int i = 0; i < 4; i++) {
            int row = l_row + i * 32;
            cp_async16(As + row * (SK * 4) + l_k4 * 16, gA + (size_t)row * IC + l_k4 * 4);
        }
#pragma unroll
        for (int i = 0; i < 4; i++) {
            int row = l_row + i * 32;
            cp_async16(Bs + row * (SK * 4) + l_k4 * 16, gB + (size_t)row * IC + l_k4 * 4);
        }
        cp_commit();
    };

    issue_chunk(0, 0);

    for (int j = 0; j < NK; j++) {
        __syncthreads();             // everyone done reading buf[(j+1)&1] (chunk j-1)
        if (j + 1 < NK) issue_chunk(j + 1, (j + 1) & 1);
        if (j + 1 < NK) asm volatile("cp.async.wait_group 1;" ::: "memory");
        else            asm volatile("cp.async.wait_group 0;" ::: "memory");
        __syncthreads();

        const float* sAf = dsm + (j & 1) * (2 * 128 * SK);
        const float* sBf = sAf + 128 * SK;
        const float* apb = sAf + (wm * 64 + r) * SK + cth;
        const float* bpb = sBf + (wn * 32 + r) * SK + cth;
#pragma unroll
        for (int ks = 0; ks < 4; ks++) {
            int k0 = ks * 8;
            uint32_t a[4][4], b[4][2];
#pragma unroll
            for (int mt = 0; mt < 4; mt++) {
                const float* ap = apb + mt * 16 * SK + k0;
                a[mt][0] = __float_as_uint(ap[0]);
                a[mt][1] = __float_as_uint(ap[8 * SK]);
                a[mt][2] = __float_as_uint(ap[4]);
                a[mt][3] = __float_as_uint(ap[8 * SK + 4]);
            }
#pragma unroll
            for (int nt = 0; nt < 4; nt++) {
                const float* bp = bpb + nt * 8 * SK + k0;
                b[nt][0] = __float_as_uint(bp[0]);
                b[nt][1] = __float_as_uint(bp[4]);
            }
#pragma unroll
            for (int mt = 0; mt < 4; mt++)
#pragma unroll
                for (int nt = 0; nt < 4; nt++)
                    mma_tf32_16x8x8(c[mt][nt], a[mt], b[nt]);
        }
    }

    // ---- epilogue: bias + relu, scatter to NHWC ----
#pragma unroll
    for (int nt = 0; nt < 4; nt++) {
        int nglob = ocbase + wn * 32 + nt * 8 + cth * 2;
        float b0 = __ldg(bias + nglob);
        float b1 = __ldg(bias + nglob + 1);
#pragma unroll
        for (int mt = 0; mt < 4; mt++) {
#pragma unroll
            for (int half = 0; half < 2; half++) {
                int q = q0 + wm * 64 + mt * 16 + r + half * 8;
                int Y = q / PW, X = q - Y * PW;
                if (X < 129 && Y < 129) {
                    float v0 = fmaxf(c[mt][nt][half * 2 + 0] + b0, 0.0f);
                    float v1 = fmaxf(c[mt][nt][half * 2 + 1] + b1, 0.0f);
                    float* dst;
                    if (TO_CCAT) {
                        v0 = tf32r(v0); v1 = tf32r(v1);
                        dst = outbuf + ((size_t)(img >> 1) * PADROWS
                              + (size_t)(Y + 1) * PW + (X + 1)) * 512
                              + (img & 1) * 256 + nglob;
                    } else {
                        dst = outbuf + ((size_t)img * NPIX + (size_t)Y * W129 + X) * 256 + nglob;
                    }
                    *reinterpret_cast<float2*>(dst) = make_float2(v0, v1);
                }
            }
        }
    }
}

// -------- 1x1 conv (NHWC input) + bias + relu + softmax ---------------------
__global__ __launch_bounds__(256) void conv1x1_softmax_nhwc(
        const float* __restrict__ yb, const float* __restrict__ w,
        const float* __restrict__ bias, float* __restrict__ ker) {
    __shared__ float s_w[49 * 128];
    const int img = blockIdx.y;
    int p = blockIdx.x * 256 + threadIdx.x;
    const bool valid = p < NPIX;
    int pc = valid ? p : NPIX - 1;
    const float* xr = yb + ((size_t)img * NPIX + pc) * 256;

    float acc[49];
#pragma unroll
    for (int o = 0; o < 49; o++) acc[o] = 0.0f;

    for (int ic0 = 0; ic0 < 256; ic0 += 128) {
        __syncthreads();
        for (int idx = threadIdx.x; idx < 49 * 128; idx += 256) {
            int o = idx >> 7, i = idx & 127;
            s_w[idx] = w[o * 256 + ic0 + i];
        }
        __syncthreads();
#pragma unroll 2
        for (int i = 0; i < 128; i += 4) {
            float4 x4 = *reinterpret_cast<const float4*>(xr + ic0 + i);
#pragma unroll
            for (int o = 0; o < 49; o++) {
                const float* wp = &s_w[o * 128 + i];
                acc[o] += x4.x * wp[0] + x4.y * wp[1] + x4.z * wp[2] + x4.w * wp[3];
            }
        }
    }
    float m = -1e30f;
#pragma unroll
    for (int o = 0; o < 49; o++) {
        acc[o] = fmaxf(acc[o] + bias[o], 0.0f);
        m = fmaxf(m, acc[o]);
    }
    float sum = 0.0f;
#pragma unroll
    for (int o = 0; o < 49; o++) {
        acc[o] = expf(acc[o] - m);
        sum += acc[o];
    }
    float inv = 1.0f / sum;
    if (valid) {
        float* k_img = ker + (size_t)img * 49 * NPIX;
#pragma unroll
        for (int o = 0; o < 49; o++)
            k_img[(size_t)o * NPIX + p] = acc[o] * inv;
    }
}

// -------- spatially-variant 7x7 conv (unchanged, passing) -------------------
__global__ __launch_bounds__(256) void svconv_kernel(const float* __restrict__ f,
                              const float* __restrict__ ker,
                              float* __restrict__ out) {
    __shared__ float s_f[8][22][22];
    const int tx = threadIdx.x & 15, ty = threadIdx.x >> 4;
    const int col0 = blockIdx.x * 16, row0 = blockIdx.y * 16;
    const int z = blockIdx.z;
    const int c_base = (z & 3) * 64;
    const int img = z >> 2;

    const int gy = row0 + ty, gx = col0 + tx;
    const bool valid = (gy < 129) && (gx < 129);
    const float* f_img = f   + (size_t)img * 256 * NPIX;
    const float* k_img = ker + (size_t)img * 49  * NPIX;
    float*       o_img = out + (size_t)img * 256 * NPIX;

    float kv[49];
    int pclamp = valid ? gy * W129 + gx : 0;
#pragma unroll
    for (int o = 0; o < 49; o++) kv[o] = k_img[(size_t)o * NPIX + pclamp];

    for (int cc = 0; cc < 64; cc += 8) {
        __syncthreads();
        for (int idx = threadIdx.x; idx < 8 * 22 * 22; idx += 256) {
            int cx = idx % 22;
            int cy = (idx / 22) % 22;
            int ch = idx / 484;
            int gr = row0 - 3 + cy, gc = col0 - 3 + cx;
            float v = 0.0f;
            if ((unsigned)gr < 129u && (unsigned)gc < 129u)
                v = f_img[(size_t)(c_base + cc + ch) * NPIX + gr * W129 + gc];
            s_f[ch][cy][cx] = v;
        }
        __syncthreads();
#pragma unroll 1
        for (int ch = 0; ch < 8; ch++) {
            float acc = 0.0f;
#pragma unroll
            for (int i = 0; i < 7; i++)
#pragma unroll
                for (int j = 0; j < 7; j++)
                    acc += kv[i * 7 + j] * s_f[ch][ty + i][tx + j];
            if (valid)
                o_img[(size_t)(c_base + cc + ch) * NPIX + gy * W129 + gx] = acc;
        }
    }
}

// ========================= launch ============================================
extern "C" void kernel_launch(void* const* d_in, const int* in_sizes, int n_in,
                              void* d_out, int out_size) {
    const float* cur      = (const float*)d_in[0];
    const float* key      = (const float*)d_in[1];
    const float* high     = (const float*)d_in[2];
    const float* w_reduce = (const float*)d_in[3];
    const float* b_reduce = (const float*)d_in[4];
    const float* w_conv2  = (const float*)d_in[5];
    const float* b_conv2  = (const float*)d_in[6];
    const float* w_conv3  = (const float*)d_in[7];
    const float* b_conv3  = (const float*)d_in[8];
    float* out = (float*)d_out;

    float *ups, *ccat, *wtr, *wt2, *yb, *kb;
    cudaGetSymbolAddress((void**)&ups,  g_ups);
    cudaGetSymbolAddress((void**)&ccat, g_ccat);
    cudaGetSymbolAddress((void**)&wtr,  g_wtr);
    cudaGetSymbolAddress((void**)&wt2,  g_wt2);
    cudaGetSymbolAddress((void**)&yb,   g_y);
    cudaGetSymbolAddress((void**)&kb,   g_ker);

    const int SMEM_DYN = 2 * BUFBYTES;   // 73728
    cudaFuncSetAttribute(conv_mma_kernel<128, true>,
                         cudaFuncAttributeMaxDynamicSharedMemorySize, SMEM_DYN);
    cudaFuncSetAttribute(conv_mma_kernel<512, false>,
                         cudaFuncAttributeMaxDynamicSharedMemorySize, SMEM_DYN);

    // 1. zero padded NHWC buffers (halos + garbage tail must read 0)
    zero_kernel<<<2048, 256>>>((float4*)ups,  (size_t)4 * PADROWS * 128 / 4,
                               (float4*)ccat, (size_t)2 * PADROWS * 512 / 4);
    // 2. weights -> [rs][oc][ic], tf32
    {
        int t1 = 9 * 256 * 128;
        transpose_w_tf32<<<(t1 + 255) / 256, 256>>>(w_reduce, wtr, 128);
        int t2 = 9 * 256 * 512;
        transpose_w_tf32<<<(t2 + 255) / 256, 256>>>(w_conv2, wt2, 512);
    }
    // 3. bilinear upsample -> NHWC padded, tf32
    {
        dim3 grid(129, 4);
        upsample_nhwc<<<grid, 256>>>(cur, key, ups);
    }
    // 4. conv_reduce: 4 imgs, IC=128 -> ccat (NHWC padded, tf32)
    {
        dim3 grid(MT128, 4, 2);
        conv_mma_kernel<128, true><<<grid, 256, SMEM_DYN>>>(ups, wtr, b_reduce, ccat);
    }
    // 5. conv2: 2 imgs, IC=512 -> y (NHWC, fp32)
    {
        dim3 grid(MT128, 2, 2);
        conv_mma_kernel<512, false><<<grid, 256, SMEM_DYN>>>(ccat, wt2, b_conv2, yb);
    }
    // 6. 1x1 conv + softmax -> kernels
    {
        dim3 grid((NPIX + 255) / 256, 2);
        conv1x1_softmax_nhwc<<<grid, 256>>>(yb, w_conv3, b_conv3, kb);
    }
    // 7. spatially-variant 7x7 conv -> output
    {
        dim3 grid(9, 9, 8);
        svconv_kernel<<<grid, 256>>>(high, kb, out);
    }
}